// round 6
// baseline (speedup 1.0000x reference)
#include <cuda_runtime.h>
#include <cstdint>
#include <cstddef>

constexpr int kD  = 256;
constexpr int kN  = 1024;
constexpr int kNP = 384;
constexpr int kNE = 384;
constexpr int kNC = 14;
constexpr int kPairs = kNP * kNE;

// ---------------- scratch layout -------------------------------------------
constexpr size_t OF_Z1   = 0;
constexpr size_t OF_SC   = OF_Z1   + (size_t)kPairs * kD;
constexpr size_t OF_ACOL = OF_SC   + (size_t)kNP * kNE * kNE;
constexpr size_t OF_U    = OF_ACOL + (size_t)kPairs;
constexpr size_t OF_V    = OF_U    + (size_t)kPairs;
constexpr size_t OF_RMAX = OF_V    + (size_t)kPairs;
constexpr size_t OF_RINV = OF_RMAX + (size_t)kPairs;
constexpr size_t OF_Y1   = OF_RINV + (size_t)kPairs;
constexpr size_t OF_Y2   = OF_Y1   + (size_t)kNP * kD;
constexpr size_t OF_T    = OF_Y2   + (size_t)kNP * kD;
constexpr size_t OF_M    = OF_T    + (size_t)kNP * kD;
constexpr size_t OF_WQ   = OF_M    + (size_t)2 * kD * kD;
constexpr size_t OF_WK   = OF_WQ   + (size_t)kD * kD;
constexpr size_t OF_WV   = OF_WK   + (size_t)kD * kD;
constexpr size_t OF_WQKG = OF_WV   + (size_t)kD * kD;          // [256][512]
constexpr size_t OF_HPW1A= OF_WQKG + (size_t)kD * 2 * kD;
constexpr size_t OF_HEW1B= OF_HPW1A+ (size_t)kNP * kD;
constexpr size_t OF_HPWL = OF_HEW1B+ (size_t)kNE * kD;
constexpr size_t OF_HEWR = OF_HPWL + (size_t)kNP * kD;
constexpr size_t OF_CVEC = OF_HEWR + (size_t)kNE * kD;
constexpr size_t OF_BQ   = OF_CVEC + kD;
constexpr size_t OF_BK   = OF_BQ   + kD;
constexpr size_t OF_BV   = OF_BK   + kD;
constexpr size_t OF_BG   = OF_BV   + kD;
constexpr size_t OF_VQ   = OF_BG   + kD;
constexpr size_t OF_VK   = OF_VQ   + kD;
constexpr size_t OF_XP   = OF_VK   + kD;
constexpr size_t OF_XE   = OF_XP   + (size_t)kNP * 3;
constexpr size_t OF_C0   = OF_XE   + (size_t)kNE * 3;
constexpr size_t OF_WMIX = OF_C0   + 1;
constexpr size_t OF_U512 = ((OF_WMIX + 1 + 3) / 4) * 4;   // U[pairs,512]; later QG[pairs,512]
constexpr size_t BUF_TOTAL = OF_U512 + (size_t)kPairs * 512;

__device__ float g_buf[BUF_TOTAL];
__device__ int   g_ibuf[kNP + kNE + kN];

// ---------------- fast math (FMA-pipe, no MUFU) ------------------------------
__device__ __forceinline__ float fexpf_(float x) {
    x = fminf(fmaxf(x, -80.f), 80.f);
    float t = fmaf(x, 1.4426950409f, 12582912.0f);
    int ni = __float_as_int(t) - 0x4B400000;
    float n = t - 12582912.0f;
    float f = fmaf(x, 1.4426950409f, -n);
    float r = 1.3333558e-3f;
    r = fmaf(r, f, 9.6181291e-3f);
    r = fmaf(r, f, 5.5504109e-2f);
    r = fmaf(r, f, 2.4022650e-1f);
    r = fmaf(r, f, 6.9314718e-1f);
    r = fmaf(r, f, 1.0f);
    return r * __int_as_float((ni + 127) << 23);
}
__device__ __forceinline__ float frcpf_(float a) {
    float y = __int_as_float(0x7EF311C3 - __float_as_int(a));
    y = y * fmaf(-a, y, 2.0f);
    y = y * fmaf(-a, y, 2.0f);
    y = y * fmaf(-a, y, 2.0f);
    return y;
}
__device__ __forceinline__ float fsigm(float x) { return frcpf_(1.f + fexpf_(-x)); }
__device__ __forceinline__ float fsilu(float x) { return x * fsigm(x); }
__device__ __forceinline__ unsigned f2tf(float f) {
    unsigned u; asm("cvt.rna.tf32.f32 %0, %1;" : "=r"(u) : "f"(f)); return u;
}
__device__ __forceinline__ float rtf(float f) { return __uint_as_float(f2tf(f)); }

// ---------------- setup -----------------------------------------------------
__global__ void k_setup(const float* __restrict__ X,
                        const unsigned char* __restrict__ pm,
                        const unsigned char* __restrict__ em,
                        const float* __restrict__ simw)
{
    __shared__ int s_mode;
    int tid = threadIdx.x, lane = tid & 31, warp = tid >> 5;
    if (warp == 0) {
        const float* pf = (const float*)pm;
        int cf = 0, adj = 0;
        for (int i = lane; i < kN; i += 32)
            cf += (pf[i] > 0.5f && pf[i] < 1.5f) ? 1 : 0;
        for (int i = lane; i + 1 < kN; i += 32)
            adj |= (pm[i] && pm[i + 1]) ? 1 : 0;
        #pragma unroll
        for (int o = 16; o; o >>= 1) {
            cf  += __shfl_xor_sync(0xffffffffu, cf, o);
            adj |= __shfl_xor_sync(0xffffffffu, adj, o);
        }
        if (lane == 0) {
            s_mode = (cf == kNP) ? 2 : (adj ? 0 : 1);
            g_buf[OF_WMIX] = fsigm(simw[0]);
        }
    }
    __syncthreads();
    int mode = s_mode;
    if (warp < 2) {
        const unsigned char* m8 = warp ? em : pm;
        const int*   mi = (const int*)m8;
        const float* mf = (const float*)m8;
        int base = 0, off = warp ? kNP : 0;
        for (int c = 0; c < kN / 32; c++) {
            int i = c * 32 + lane;
            bool on = (mode == 0) ? (m8[i] != 0) : (mode == 1) ? (mi[i] != 0) : (mf[i] > 0.5f);
            unsigned b = __ballot_sync(0xffffffffu, on);
            int pos = base + __popc(b & ((1u << lane) - 1));
            if (on && pos < ((warp) ? kNE : kNP)) g_ibuf[off + pos] = i;
            base += __popc(b);
        }
    }
    __syncthreads();
    for (int i = tid; i < kN; i += blockDim.x) g_ibuf[kNP + kNE + i] = -1;
    __syncthreads();
    for (int i = tid; i < kNP; i += blockDim.x) {
        int n = g_ibuf[i];
        g_ibuf[kNP + kNE + n] = i;
        g_buf[OF_XP + i*3 + 0] = X[(size_t)n * kNC * 3 + 3 + 0];
        g_buf[OF_XP + i*3 + 1] = X[(size_t)n * kNC * 3 + 3 + 1];
        g_buf[OF_XP + i*3 + 2] = X[(size_t)n * kNC * 3 + 3 + 2];
    }
    for (int i = tid; i < kNE; i += blockDim.x) {
        int n = g_ibuf[kNP + i];
        g_buf[OF_XE + i*3 + 0] = X[(size_t)n * kNC * 3 + 3 + 0];
        g_buf[OF_XE + i*3 + 1] = X[(size_t)n * kNC * 3 + 3 + 1];
        g_buf[OF_XE + i*3 + 2] = X[(size_t)n * kNC * 3 + 3 + 2];
    }
}

// ---------------- folded bias vectors ----------------------------------------
__global__ void k_vectors(const float* __restrict__ res_b2, const float* __restrict__ atom_b2,
                          const float* __restrict__ int_w1, const float* __restrict__ int_b1,
                          const float* __restrict__ int_b2,
                          const float* __restrict__ wq_w, const float* __restrict__ wq_b,
                          const float* __restrict__ wk_w, const float* __restrict__ wk_b,
                          const float* __restrict__ wv_w, const float* __restrict__ wv_b,
                          const float* __restrict__ wg_w, const float* __restrict__ wg_b)
{
    int d = threadIdx.x;
    float wmix = g_buf[OF_WMIX], wm1 = 1.f - wmix;
    const float* W1c = int_w1 + 2 * kD * kD;
    float c = 0.f, bq = 0.f, bk = 0.f, bv = 0.f, bg = 0.f;
    for (int j = 0; j < kD; j++) {
        c  += (wmix * res_b2[j] + wm1 * atom_b2[j]) * W1c[(size_t)j * kD + d];
        float b2 = int_b2[j];
        bq += b2 * wq_w[(size_t)j * kD + d];
        bk += b2 * wk_w[(size_t)j * kD + d];
        bv += b2 * wv_w[(size_t)j * kD + d];
        bg += b2 * wg_w[(size_t)j * kD + d];
    }
    g_buf[OF_CVEC + d] = c + int_b1[d];
    g_buf[OF_BQ + d] = bq + wq_b[d];
    g_buf[OF_BK + d] = bk + wk_b[d];
    g_buf[OF_BV + d] = bv + wv_b[d];
    g_buf[OF_BG + d] = bg + wg_b[d];
}

// vq[d] = Wq'[d,:].bk', vk[d] = Wk'[d,:].bq', c0 = bq'.bk'  (grid 256)
__global__ void k_vqvk()
{
    int d = blockIdx.x, j = threadIdx.x;
    __shared__ float r1[256], r2[256], r3[256];
    r1[j] = g_buf[OF_WQ + (size_t)d * kD + j] * g_buf[OF_BK + j];
    r2[j] = g_buf[OF_WK + (size_t)d * kD + j] * g_buf[OF_BQ + j];
    r3[j] = (d == 0) ? g_buf[OF_BQ + j] * g_buf[OF_BK + j] : 0.f;
    __syncthreads();
    for (int s = 128; s; s >>= 1) {
        if (j < s) { r1[j] += r1[j+s]; r2[j] += r2[j+s]; r3[j] += r3[j+s]; }
        __syncthreads();
    }
    if (j == 0) {
        g_buf[OF_VQ + d] = r1[0];
        g_buf[OF_VK + d] = r2[0];
        if (d == 0) g_buf[OF_C0] = r3[0];
    }
}

// ---------------- batched small fp32 GEMM (K=256) -----------------------------
struct GDesc {
    const float* A; const int* rowidx; const float* B; const float* bias;
    float* C; int transB; int scale_mode; int M; int ldc; int round;
};
struct GBatch { GDesc d[10]; };

__global__ void __launch_bounds__(256) k_gemm_b(GBatch gbb)
{
    GDesc g = gbb.d[blockIdx.z];
    int row0 = blockIdx.y * 64, col0 = blockIdx.x * 64;
    if (row0 >= g.M) return;
    __shared__ float As[8][68];
    __shared__ float Bs[8][68];
    int tid = threadIdx.x;
    int ty = tid >> 4, tx = tid & 15;
    float acc[4][4] = {};
    for (int k0 = 0; k0 < kD; k0 += 8) {
        #pragma unroll
        for (int q = 0; q < 2; q++) {
            int t = tid + q * 256;
            int r = t >> 3, kk = t & 7;
            int arow = g.rowidx ? g.rowidx[row0 + r] : (row0 + r);
            As[kk][r] = g.A[(size_t)arow * kD + k0 + kk];
            if (!g.transB) {
                int kk2 = t >> 6, c = t & 63;
                Bs[kk2][c] = g.B[(size_t)(k0 + kk2) * kD + col0 + c];
            } else {
                Bs[kk][r] = g.B[(size_t)(col0 + r) * kD + k0 + kk];
            }
        }
        __syncthreads();
        #pragma unroll
        for (int kk = 0; kk < 8; kk++) {
            float4 a4 = *(const float4*)&As[kk][ty * 4];
            float4 b4 = *(const float4*)&Bs[kk][tx * 4];
            float av[4] = {a4.x, a4.y, a4.z, a4.w};
            float bv[4] = {b4.x, b4.y, b4.z, b4.w};
            #pragma unroll
            for (int i = 0; i < 4; i++)
                #pragma unroll
                for (int j = 0; j < 4; j++)
                    acc[i][j] += av[i] * bv[j];
        }
        __syncthreads();
    }
    float scale = (g.scale_mode == 0) ? g_buf[OF_WMIX]
                : (g.scale_mode == 1) ? (1.f - g_buf[OF_WMIX]) : 1.f;
    #pragma unroll
    for (int i = 0; i < 4; i++) {
        int r = row0 + ty * 4 + i, c = col0 + tx * 4;
        float4 o;
        o.x = acc[i][0] * scale + (g.bias ? g.bias[c + 0] : 0.f);
        o.y = acc[i][1] * scale + (g.bias ? g.bias[c + 1] : 0.f);
        o.z = acc[i][2] * scale + (g.bias ? g.bias[c + 2] : 0.f);
        o.w = acc[i][3] * scale + (g.bias ? g.bias[c + 3] : 0.f);
        if (g.round) { o.x = rtf(o.x); o.y = rtf(o.y); o.z = rtf(o.z); o.w = rtf(o.w); }
        *(float4*)&g.C[(size_t)r * g.ldc + c] = o;
    }
}

// ---------------- U[pairs,512] (tf32-rounded) ---------------------------------
__global__ void __launch_bounds__(256) k_u512(const float* __restrict__ rw1, const float* __restrict__ rb1,
                                              const float* __restrict__ aw1, const float* __restrict__ ab1)
{
    int pair = blockIdx.x * 2 + (threadIdx.x >> 7);
    int j = threadIdx.x & 127;
    int p = pair / kNE, e = pair % kNE;
    float dx = g_buf[OF_XP + p*3 + 0] - g_buf[OF_XE + e*3 + 0];
    float dy = g_buf[OF_XP + p*3 + 1] - g_buf[OF_XE + e*3 + 1];
    float dz = g_buf[OF_XP + p*3 + 2] - g_buf[OF_XE + e*3 + 2];
    float S = dx*dx + dy*dy + dz*dz;
    int k = j * 4;
    const float* w = (k < kD) ? (rw1 + k) : (aw1 + k - kD);
    const float* b = (k < kD) ? (rb1 + k) : (ab1 + k - kD);
    float4 o;
    o.x = rtf(fsilu(S * w[0] + b[0]));
    o.y = rtf(fsilu(S * w[1] + b[1]));
    o.z = rtf(fsilu(S * w[2] + b[2]));
    o.w = rtf(fsilu(S * w[3] + b[3]));
    *(float4*)&g_buf[OF_U512 + (size_t)pair * 512 + k] = o;
}

// ---------------- tf32 tensor-core GEMM ---------------------------------------
// All operands pre-rounded to tf32 -> raw bit loads, no cvt in the hot loop.
struct MArgs {
    const float* A; const float* B; float* C;
    int K, lda, ldb, ldc, transB, mode, round;
    long sA, sB, sC;
};

__device__ __forceinline__ void mma_tf32(float (&c)[4], const unsigned (&a)[4], const unsigned (&b)[2])
{
    asm volatile(
        "mma.sync.aligned.m16n8k8.row.col.f32.tf32.tf32.f32 "
        "{%0,%1,%2,%3}, {%4,%5,%6,%7}, {%8,%9}, {%0,%1,%2,%3};"
        : "+f"(c[0]), "+f"(c[1]), "+f"(c[2]), "+f"(c[3])
        : "r"(a[0]), "r"(a[1]), "r"(a[2]), "r"(a[3]), "r"(b[0]), "r"(b[1]));
}

__global__ void __launch_bounds__(128) k_mma(MArgs ar)
{
    __shared__ unsigned As[16][72];
    __shared__ unsigned Bs[16][72];
    int z = blockIdx.z;
    const float* A = ar.A + (size_t)z * ar.sA;
    const float* B = ar.B + (size_t)z * ar.sB;
    float*       C = ar.C + (size_t)z * ar.sC;
    int tid = threadIdx.x;
    int warp = tid >> 5, lane = tid & 31;
    int gg = lane >> 2, tig = lane & 3;
    int wm = warp & 1, wn = warp >> 1;
    int row0 = blockIdx.y * 64, col0 = blockIdx.x * 64;
    float c[2][4][4] = {};
    for (int k0 = 0; k0 < ar.K; k0 += 16) {
        #pragma unroll
        for (int q = 0; q < 2; q++) {
            int t = tid + q * 128;
            int r = t >> 2, cc = (t & 3) * 4;
            float4 a4 = *(const float4*)&A[(size_t)(row0 + r) * ar.lda + k0 + cc];
            As[cc + 0][r] = __float_as_uint(a4.x);
            As[cc + 1][r] = __float_as_uint(a4.y);
            As[cc + 2][r] = __float_as_uint(a4.z);
            As[cc + 3][r] = __float_as_uint(a4.w);
            if (!ar.transB) {
                int kk = t >> 4, c2 = (t & 15) * 4;
                float4 b4 = *(const float4*)&B[(size_t)(k0 + kk) * ar.ldb + col0 + c2];
                uint4 u;
                u.x = __float_as_uint(b4.x); u.y = __float_as_uint(b4.y);
                u.z = __float_as_uint(b4.z); u.w = __float_as_uint(b4.w);
                *(uint4*)&Bs[kk][c2] = u;
            } else {
                float4 b4 = *(const float4*)&B[(size_t)(col0 + r) * ar.ldb + k0 + cc];
                Bs[cc + 0][r] = __float_as_uint(b4.x);
                Bs[cc + 1][r] = __float_as_uint(b4.y);
                Bs[cc + 2][r] = __float_as_uint(b4.z);
                Bs[cc + 3][r] = __float_as_uint(b4.w);
            }
        }
        __syncthreads();
        #pragma unroll
        for (int ks = 0; ks < 2; ks++) {
            unsigned af[2][4], bf[4][2];
            #pragma unroll
            for (int i = 0; i < 2; i++) {
                int m = wm * 32 + i * 16;
                af[i][0] = As[ks*8 + tig    ][m + gg    ];
                af[i][1] = As[ks*8 + tig    ][m + gg + 8];
                af[i][2] = As[ks*8 + tig + 4][m + gg    ];
                af[i][3] = As[ks*8 + tig + 4][m + gg + 8];
            }
            #pragma unroll
            for (int j = 0; j < 4; j++) {
                int n = wn * 32 + j * 8;
                bf[j][0] = Bs[ks*8 + tig    ][n + gg];
                bf[j][1] = Bs[ks*8 + tig + 4][n + gg];
            }
            #pragma unroll
            for (int i = 0; i < 2; i++)
                #pragma unroll
                for (int j = 0; j < 4; j++)
                    mma_tf32(c[i][j], af[i], bf[j]);
        }
        __syncthreads();
    }
    #pragma unroll
    for (int i = 0; i < 2; i++) {
        #pragma unroll
        for (int j = 0; j < 4; j++) {
            int r0 = row0 + wm * 32 + i * 16 + gg;
            int cc = col0 + wn * 32 + j * 8 + tig * 2;
            #pragma unroll
            for (int h = 0; h < 2; h++) {
                int r = r0 + h * 8;
                float v0 = c[i][j][h * 2], v1 = c[i][j][h * 2 + 1];
                if (ar.mode == 1) {
                    int p = r / kNE, e = r - p * kNE;
                    v0 = fsilu(v0 + g_buf[OF_CVEC + cc]     + g_buf[OF_HPW1A + (size_t)p*kD + cc]
                                   + g_buf[OF_HEW1B + (size_t)e*kD + cc]);
                    v1 = fsilu(v1 + g_buf[OF_CVEC + cc + 1] + g_buf[OF_HPW1A + (size_t)p*kD + cc + 1]
                                   + g_buf[OF_HEW1B + (size_t)e*kD + cc + 1]);
                } else if (ar.mode == 2) {
                    float add = g_buf[OF_U + (size_t)z*kNE + r] + g_buf[OF_C0];
                    v0 = (v0 + add + g_buf[OF_V + (size_t)z*kNE + cc]) * 0.0625f;
                    v1 = (v1 + add + g_buf[OF_V + (size_t)z*kNE + cc + 1]) * 0.0625f;
                }
                if (ar.round) { v0 = rtf(v0); v1 = rtf(v1); }
                float2 o; o.x = v0; o.y = v1;
                *(float2*)&C[(size_t)r * ar.ldc + cc] = o;
            }
        }
    }
}

// ---------------- u,v per pair --------------------------------------------------
__global__ void __launch_bounds__(256) k_uv()
{
    int warp = threadIdx.x >> 5, lane = threadIdx.x & 31;
    size_t pair = (size_t)blockIdx.x * 8 + warp;
    const float* zz = g_buf + OF_Z1 + pair * kD;
    float su = 0.f, sv = 0.f;
    #pragma unroll
    for (int q = 0; q < 8; q++) {
        int d = lane + q * 32;
        float zv = zz[d];
        su += zv * g_buf[OF_VQ + d];
        sv += zv * g_buf[OF_VK + d];
    }
    #pragma unroll
    for (int o = 16; o; o >>= 1) {
        su += __shfl_xor_sync(0xffffffffu, su, o);
        sv += __shfl_xor_sync(0xffffffffu, sv, o);
    }
    if (lane == 0) { g_buf[OF_U + pair] = su; g_buf[OF_V + pair] = sv; }
}

// ---------------- softmax row stats (no A write-back) ----------------------------
__global__ void __launch_bounds__(256) k_rowstats()
{
    int warp = threadIdx.x >> 5, lane = threadIdx.x & 31;
    size_t row = (size_t)blockIdx.x * 8 + warp;
    const float* s = g_buf + OF_SC + row * kNE;
    float v[12];
    float mx = -1e30f;
    #pragma unroll
    for (int i = 0; i < 12; i++) { v[i] = s[lane + 32*i]; mx = fmaxf(mx, v[i]); }
    #pragma unroll
    for (int o = 16; o; o >>= 1) mx = fmaxf(mx, __shfl_xor_sync(0xffffffffu, mx, o));
    float sum = 0.f;
    #pragma unroll
    for (int i = 0; i < 12; i++) sum += fexpf_(v[i] - mx);
    #pragma unroll
    for (int o = 16; o; o >>= 1) sum += __shfl_xor_sync(0xffffffffu, sum, o);
    if (lane == 0) {
        g_buf[OF_RMAX + row] = mx;
        g_buf[OF_RINV + row] = frcpf_(sum);
    }
}

// acol[p,f] = (1/NE) sum_e exp(sc-mx[e])*rinv[e]
__global__ void __launch_bounds__(256) k_acol()
{
    int idx = blockIdx.x * 256 + threadIdx.x;
    int p = idx / kNE, f = idx - p * kNE;
    const float* base = g_buf + OF_SC + (size_t)p * kNE * kNE + f;
    const float* rm = g_buf + OF_RMAX + (size_t)p * kNE;
    const float* ri = g_buf + OF_RINV + (size_t)p * kNE;
    float s = 0.f;
    #pragma unroll 8
    for (int e = 0; e < kNE; e++)
        s += fexpf_(base[(size_t)e * kNE] - rm[e]) * ri[e];
    g_buf[OF_ACOL + idx] = s * (1.f / kNE);
}

// ---------------- y1[p,d] = sum_f acol[p,f] Z1[p,f,d] -----------------------------
__global__ void __launch_bounds__(256) k_y1()
{
    int p = blockIdx.x, d = threadIdx.x;
    __shared__ float ac[kNE];
    for (int i = d; i < kNE; i += 256) ac[i] = g_buf[OF_ACOL + (size_t)p * kNE + i];
    __syncthreads();
    float s = 0.f;
    const float* zz = g_buf + OF_Z1 + (size_t)p * kNE * kD + d;
    #pragma unroll 8
    for (int f = 0; f < kNE; f++) s += ac[f] * zz[(size_t)f * kD];
    g_buf[OF_Y1 + (size_t)p * kD + d] = s;
}

// ---------------- gate reduce (reads G = QG[:,256:512]) ----------------------------
__global__ void __launch_bounds__(256) k_gate_red()
{
    int p = blockIdx.x, d = threadIdx.x;
    const float* G = g_buf + OF_U512 + (size_t)p * kNE * 512 + 256 + d;
    const float* hw = g_buf + OF_HEWR + d;
    float bg = g_buf[OF_BG + d];
    float s = 0.f;
    #pragma unroll 4
    for (int e = 0; e < kNE; e++)
        s += fsigm(G[(size_t)e * 512] + bg) * hw[(size_t)e * kD];
    g_buf[OF_T + (size_t)p * kD + d] = s;
}

// ---------------- final --------------------------------------------------------------
__global__ void k_final(const float* __restrict__ H, float* __restrict__ out)
{
    int n = blockIdx.x, d = threadIdx.x;
    int p = g_ibuf[kNP + kNE + n];
    float v = H[(size_t)n * kD + d];
    if (p >= 0)
        v = g_buf[OF_HPWL + (size_t)p * kD + d] * g_buf[OF_T + (size_t)p * kD + d] * (1.f / kNE)
          + g_buf[OF_Y2 + (size_t)p * kD + d];
    out[(size_t)n * kD + d] = v;
}

// ---------------- launch --------------------------------------------------------------
extern "C" void kernel_launch(void* const* d_in, const int* in_sizes, int n_in,
                              void* d_out, int out_size)
{
    const float* H   = (const float*)d_in[0];
    const float* X   = (const float*)d_in[1];
    const unsigned char* pm = (const unsigned char*)d_in[2];
    const unsigned char* em = (const unsigned char*)d_in[3];
    const float* rw1 = (const float*)d_in[4];
    const float* rb1 = (const float*)d_in[5];
    const float* rw2 = (const float*)d_in[6];
    const float* rb2 = (const float*)d_in[7];
    const float* aw1 = (const float*)d_in[8];
    const float* ab1 = (const float*)d_in[9];
    const float* aw2 = (const float*)d_in[10];
    const float* ab2 = (const float*)d_in[11];
    const float* simw= (const float*)d_in[12];
    const float* iw1 = (const float*)d_in[13];
    const float* ib1 = (const float*)d_in[14];
    const float* iw2 = (const float*)d_in[15];
    const float* ib2 = (const float*)d_in[16];
    const float* wl  = (const float*)d_in[17];
    const float* wr  = (const float*)d_in[18];
    const float* wgw = (const float*)d_in[19];
    const float* wgb = (const float*)d_in[20];
    const float* wqw = (const float*)d_in[21];
    const float* wqb = (const float*)d_in[22];
    const float* wkw = (const float*)d_in[23];
    const float* wkb = (const float*)d_in[24];
    const float* wvw = (const float*)d_in[25];
    const float* wvb = (const float*)d_in[26];
    float* out = (float*)d_out;

    float* gb = nullptr; int* gi = nullptr;
    cudaGetSymbolAddress((void**)&gb, g_buf);
    cudaGetSymbolAddress((void**)&gi, g_ibuf);

    k_setup<<<1, 256>>>(X, pm, em, simw);
    k_vectors<<<1, 256>>>(rb2, ab2, iw1, ib1, ib2, wqw, wqb, wkw, wkb, wvw, wvb, wgw, wgb);

    GBatch batch;
    const float* W1c = iw1 + 2 * kD * kD;
    batch.d[0] = {rw2, nullptr, W1c, nullptr, gb + OF_M,             0, 0, kD,  kD,    1};
    batch.d[1] = {aw2, nullptr, W1c, nullptr, gb + OF_M + kD*kD,     0, 1, kD,  kD,    1};
    batch.d[2] = {iw2, nullptr, wqw, nullptr, gb + OF_WQ,            0, 2, kD,  kD,    0};
    batch.d[3] = {iw2, nullptr, wkw, nullptr, gb + OF_WK,            0, 2, kD,  kD,    0};
    batch.d[4] = {iw2, nullptr, wvw, nullptr, gb + OF_WV,            0, 2, kD,  kD,    0};
    batch.d[5] = {iw2, nullptr, wgw, nullptr, gb + OF_WQKG + kD,     0, 2, kD,  2*kD,  1};
    batch.d[6] = {H, gi,        iw1,          nullptr, gb + OF_HPW1A, 0, 2, kNP, kD,   0};
    batch.d[7] = {H, gi + kNP,  iw1 + kD*kD,  nullptr, gb + OF_HEW1B, 0, 2, kNE, kD,   0};
    batch.d[8] = {H, gi,        wl,           nullptr, gb + OF_HPWL,  0, 2, kNP, kD,   0};
    batch.d[9] = {H, gi + kNP,  wr,           nullptr, gb + OF_HEWR,  0, 2, kNE, kD,   0};
    k_gemm_b<<<dim3(4, 6, 10), 256>>>(batch);

    k_vqvk<<<256, 256>>>();

    GBatch b2;
    b2.d[0] = {gb + OF_WQ, nullptr, gb + OF_WK, nullptr, gb + OF_WQKG, 1, 2, kD, 2*kD, 1};
    k_gemm_b<<<dim3(4, 4, 1), 256>>>(b2);

    k_u512<<<kPairs / 2, 256>>>(rw1, rb1, aw1, ab1);

    // Z1 = silu(U @ M + biases), tf32-rounded
    MArgs mz; mz.A = gb + OF_U512; mz.B = gb + OF_M; mz.C = gb + OF_Z1;
    mz.K = 512; mz.lda = 512; mz.ldb = kD; mz.ldc = kD;
    mz.transB = 0; mz.mode = 1; mz.round = 1; mz.sA = mz.sB = mz.sC = 0;
    k_mma<<<dim3(4, kPairs / 64, 1), 128>>>(mz);

    k_uv<<<kPairs / 8, 256>>>();

    // QG = Z1 @ [WQK | WG'] -> [pairs, 512] (reuses U512 buffer), tf32-rounded
    MArgs mq; mq.A = gb + OF_Z1; mq.B = gb + OF_WQKG; mq.C = gb + OF_U512;
    mq.K = kD; mq.lda = kD; mq.ldb = 2*kD; mq.ldc = 2*kD;
    mq.transB = 0; mq.mode = 0; mq.round = 1; mq.sA = mq.sB = mq.sC = 0;
    k_mma<<<dim3(8, kPairs / 64, 1), 128>>>(mq);

    // scores[p] = (Q[p] @ Z1[p]^T + u + v + c0) / 16
    MArgs ms; ms.A = gb + OF_U512; ms.B = gb + OF_Z1; ms.C = gb + OF_SC;
    ms.K = kD; ms.lda = 2*kD; ms.ldb = kD; ms.ldc = kNE;
    ms.transB = 1; ms.mode = 2; ms.round = 0;
    ms.sA = (long)kNE * 2 * kD; ms.sB = (long)kNE * kD; ms.sC = (long)kNE * kNE;
    k_mma<<<dim3(6, 6, kNP), 128>>>(ms);

    k_rowstats<<<kPairs / 8, 256>>>();
    k_acol<<<kPairs / 256, 256>>>();
    k_y1<<<kNP, 256>>>();

    GBatch b3;
    b3.d[0] = {gb + OF_Y1, nullptr, gb + OF_WV, gb + OF_BV, gb + OF_Y2, 0, 2, kNP, kD, 0};
    k_gemm_b<<<dim3(4, 6, 1), 256>>>(b3);

    k_gate_red<<<kNP, 256>>>();
    k_final<<<kN, 256>>>(H, out);
}

// round 7
// speedup vs baseline: 1.2021x; 1.2021x over previous
#include <cuda_runtime.h>
#include <cstdint>
#include <cstddef>

constexpr int kD  = 256;
constexpr int kN  = 1024;
constexpr int kNP = 384;
constexpr int kNE = 384;
constexpr int kNC = 14;
constexpr int kPairs = kNP * kNE;

// ---------------- scratch layout -------------------------------------------
constexpr size_t OF_Z1   = 0;
constexpr size_t OF_Q    = OF_Z1   + (size_t)kPairs * kD;
constexpr size_t OF_SC   = OF_Q    + (size_t)kPairs * kD;
constexpr size_t OF_ACOL = OF_SC   + (size_t)kNP * kNE * kNE;
constexpr size_t OF_U    = OF_ACOL + (size_t)kPairs;
constexpr size_t OF_V    = OF_U    + (size_t)kPairs;
constexpr size_t OF_RMAX = OF_V    + (size_t)kPairs;
constexpr size_t OF_RINV = OF_RMAX + (size_t)kPairs;
constexpr size_t OF_Y1   = OF_RINV + (size_t)kPairs;
constexpr size_t OF_Y2   = OF_Y1   + (size_t)kNP * kD;
constexpr size_t OF_T    = OF_Y2   + (size_t)kNP * kD;
constexpr size_t OF_M    = OF_T    + (size_t)kNP * kD;
constexpr size_t OF_WQ   = OF_M    + (size_t)2 * kD * kD;
constexpr size_t OF_WK   = OF_WQ   + (size_t)kD * kD;
constexpr size_t OF_WV   = OF_WK   + (size_t)kD * kD;
constexpr size_t OF_WQKG = OF_WV   + (size_t)kD * kD;          // [256][512]
constexpr size_t OF_HPW1A= OF_WQKG + (size_t)kD * 2 * kD;
constexpr size_t OF_HEW1B= OF_HPW1A+ (size_t)kNP * kD;
constexpr size_t OF_HPWL = OF_HEW1B+ (size_t)kNE * kD;
constexpr size_t OF_HEWR = OF_HPWL + (size_t)kNP * kD;
constexpr size_t OF_CVEC = OF_HEWR + (size_t)kNE * kD;
constexpr size_t OF_BQ   = OF_CVEC + kD;
constexpr size_t OF_BK   = OF_BQ   + kD;
constexpr size_t OF_BV   = OF_BK   + kD;
constexpr size_t OF_BG   = OF_BV   + kD;
constexpr size_t OF_VQ   = OF_BG   + kD;
constexpr size_t OF_VK   = OF_VQ   + kD;
constexpr size_t OF_XP   = OF_VK   + kD;
constexpr size_t OF_XE   = OF_XP   + (size_t)kNP * 3;
constexpr size_t OF_C0   = OF_XE   + (size_t)kNE * 3;
constexpr size_t OF_WMIX = OF_C0   + 1;
constexpr size_t BUF_TOTAL = OF_WMIX + 1;

__device__ float g_buf[BUF_TOTAL];
__device__ int   g_ibuf[kNP + kNE + kN];

// ---------------- fast math (FMA-pipe) ---------------------------------------
__device__ __forceinline__ float fexpf_(float x) {
    x = fminf(fmaxf(x, -80.f), 80.f);
    float t = fmaf(x, 1.4426950409f, 12582912.0f);
    int ni = __float_as_int(t) - 0x4B400000;
    float n = t - 12582912.0f;
    float f = fmaf(x, 1.4426950409f, -n);
    float r = 1.3333558e-3f;
    r = fmaf(r, f, 9.6181291e-3f);
    r = fmaf(r, f, 5.5504109e-2f);
    r = fmaf(r, f, 2.4022650e-1f);
    r = fmaf(r, f, 6.9314718e-1f);
    r = fmaf(r, f, 1.0f);
    return r * __int_as_float((ni + 127) << 23);
}
__device__ __forceinline__ float frcpf_(float a) {
    float y = __int_as_float(0x7EF311C3 - __float_as_int(a));
    y = y * fmaf(-a, y, 2.0f);
    y = y * fmaf(-a, y, 2.0f);
    y = y * fmaf(-a, y, 2.0f);
    return y;
}
__device__ __forceinline__ float fsigm(float x) { return frcpf_(1.f + fexpf_(-x)); }
__device__ __forceinline__ float fsilu(float x) { return x * fsigm(x); }
__device__ __forceinline__ unsigned f2tf(float f) {
    unsigned u; asm("cvt.rna.tf32.f32 %0, %1;" : "=r"(u) : "f"(f)); return u;
}
__device__ __forceinline__ float rtf(float f) { return __uint_as_float(f2tf(f)); }

// ---------------- setup -------------------------------------------------------
__global__ void k_setup(const float* __restrict__ X,
                        const unsigned char* __restrict__ pm,
                        const unsigned char* __restrict__ em,
                        const float* __restrict__ simw)
{
    __shared__ int s_mode;
    int tid = threadIdx.x, lane = tid & 31, warp = tid >> 5;
    if (warp == 0) {
        const float* pf = (const float*)pm;
        int cf = 0, adj = 0;
        for (int i = lane; i < kN; i += 32)
            cf += (pf[i] > 0.5f && pf[i] < 1.5f) ? 1 : 0;
        for (int i = lane; i + 1 < kN; i += 32)
            adj |= (pm[i] && pm[i + 1]) ? 1 : 0;
        #pragma unroll
        for (int o = 16; o; o >>= 1) {
            cf  += __shfl_xor_sync(0xffffffffu, cf, o);
            adj |= __shfl_xor_sync(0xffffffffu, adj, o);
        }
        if (lane == 0) {
            s_mode = (cf == kNP) ? 2 : (adj ? 0 : 1);
            g_buf[OF_WMIX] = fsigm(simw[0]);
        }
    }
    __syncthreads();
    int mode = s_mode;
    if (warp < 2) {
        const unsigned char* m8 = warp ? em : pm;
        const int*   mi = (const int*)m8;
        const float* mf = (const float*)m8;
        int base = 0, off = warp ? kNP : 0;
        for (int c = 0; c < kN / 32; c++) {
            int i = c * 32 + lane;
            bool on = (mode == 0) ? (m8[i] != 0) : (mode == 1) ? (mi[i] != 0) : (mf[i] > 0.5f);
            unsigned b = __ballot_sync(0xffffffffu, on);
            int pos = base + __popc(b & ((1u << lane) - 1));
            if (on && pos < ((warp) ? kNE : kNP)) g_ibuf[off + pos] = i;
            base += __popc(b);
        }
    }
    __syncthreads();
    for (int i = tid; i < kN; i += blockDim.x) g_ibuf[kNP + kNE + i] = -1;
    __syncthreads();
    for (int i = tid; i < kNP; i += blockDim.x) {
        int n = g_ibuf[i];
        g_ibuf[kNP + kNE + n] = i;
        g_buf[OF_XP + i*3 + 0] = X[(size_t)n * kNC * 3 + 3 + 0];
        g_buf[OF_XP + i*3 + 1] = X[(size_t)n * kNC * 3 + 3 + 1];
        g_buf[OF_XP + i*3 + 2] = X[(size_t)n * kNC * 3 + 3 + 2];
    }
    for (int i = tid; i < kNE; i += blockDim.x) {
        int n = g_ibuf[kNP + i];
        g_buf[OF_XE + i*3 + 0] = X[(size_t)n * kNC * 3 + 3 + 0];
        g_buf[OF_XE + i*3 + 1] = X[(size_t)n * kNC * 3 + 3 + 1];
        g_buf[OF_XE + i*3 + 2] = X[(size_t)n * kNC * 3 + 3 + 2];
    }
}

// ---------------- folded bias vectors ------------------------------------------
__global__ void k_vectors(const float* __restrict__ res_b2, const float* __restrict__ atom_b2,
                          const float* __restrict__ int_w1, const float* __restrict__ int_b1,
                          const float* __restrict__ int_b2,
                          const float* __restrict__ wq_w, const float* __restrict__ wq_b,
                          const float* __restrict__ wk_w, const float* __restrict__ wk_b,
                          const float* __restrict__ wv_w, const float* __restrict__ wv_b,
                          const float* __restrict__ wg_w, const float* __restrict__ wg_b)
{
    int d = threadIdx.x;
    float wmix = g_buf[OF_WMIX], wm1 = 1.f - wmix;
    const float* W1c = int_w1 + 2 * kD * kD;
    float c = 0.f, bq = 0.f, bk = 0.f, bv = 0.f, bg = 0.f;
    for (int j = 0; j < kD; j++) {
        c  += (wmix * res_b2[j] + wm1 * atom_b2[j]) * W1c[(size_t)j * kD + d];
        float b2 = int_b2[j];
        bq += b2 * wq_w[(size_t)j * kD + d];
        bk += b2 * wk_w[(size_t)j * kD + d];
        bv += b2 * wv_w[(size_t)j * kD + d];
        bg += b2 * wg_w[(size_t)j * kD + d];
    }
    g_buf[OF_CVEC + d] = c + int_b1[d];
    g_buf[OF_BQ + d] = bq + wq_b[d];
    g_buf[OF_BK + d] = bk + wk_b[d];
    g_buf[OF_BV + d] = bv + wv_b[d];
    g_buf[OF_BG + d] = bg + wg_b[d];
}

__global__ void k_vqvk()
{
    int d = blockIdx.x, j = threadIdx.x;
    __shared__ float r1[256], r2[256], r3[256];
    r1[j] = g_buf[OF_WQ + (size_t)d * kD + j] * g_buf[OF_BK + j];
    r2[j] = g_buf[OF_WK + (size_t)d * kD + j] * g_buf[OF_BQ + j];
    r3[j] = (d == 0) ? g_buf[OF_BQ + j] * g_buf[OF_BK + j] : 0.f;
    __syncthreads();
    for (int s = 128; s; s >>= 1) {
        if (j < s) { r1[j] += r1[j+s]; r2[j] += r2[j+s]; r3[j] += r3[j+s]; }
        __syncthreads();
    }
    if (j == 0) {
        g_buf[OF_VQ + d] = r1[0];
        g_buf[OF_VK + d] = r2[0];
        if (d == 0) g_buf[OF_C0] = r3[0];
    }
}

__global__ void k_zeroT()
{
    g_buf[OF_T + (size_t)blockIdx.x * 256 + threadIdx.x] = 0.f;
}

// ---------------- batched small fp32 GEMM (K=256) -------------------------------
struct GDesc {
    const float* A; const int* rowidx; const float* B; const float* bias;
    float* C; int transB; int scale_mode; int M; int ldc; int round;
};
struct GBatch { GDesc d[10]; };

__global__ void __launch_bounds__(256) k_gemm_b(GBatch gbb)
{
    GDesc g = gbb.d[blockIdx.z];
    int row0 = blockIdx.y * 64, col0 = blockIdx.x * 64;
    if (row0 >= g.M) return;
    __shared__ float As[8][68];
    __shared__ float Bs[8][68];
    int tid = threadIdx.x;
    int ty = tid >> 4, tx = tid & 15;
    float acc[4][4] = {};
    for (int k0 = 0; k0 < kD; k0 += 8) {
        #pragma unroll
        for (int q = 0; q < 2; q++) {
            int t = tid + q * 256;
            int r = t >> 3, kk = t & 7;
            int arow = g.rowidx ? g.rowidx[row0 + r] : (row0 + r);
            As[kk][r] = g.A[(size_t)arow * kD + k0 + kk];
            if (!g.transB) {
                int kk2 = t >> 6, c = t & 63;
                Bs[kk2][c] = g.B[(size_t)(k0 + kk2) * kD + col0 + c];
            } else {
                Bs[kk][r] = g.B[(size_t)(col0 + r) * kD + k0 + kk];
            }
        }
        __syncthreads();
        #pragma unroll
        for (int kk = 0; kk < 8; kk++) {
            float4 a4 = *(const float4*)&As[kk][ty * 4];
            float4 b4 = *(const float4*)&Bs[kk][tx * 4];
            float av[4] = {a4.x, a4.y, a4.z, a4.w};
            float bv[4] = {b4.x, b4.y, b4.z, b4.w};
            #pragma unroll
            for (int i = 0; i < 4; i++)
                #pragma unroll
                for (int j = 0; j < 4; j++)
                    acc[i][j] += av[i] * bv[j];
        }
        __syncthreads();
    }
    float scale = (g.scale_mode == 0) ? g_buf[OF_WMIX]
                : (g.scale_mode == 1) ? (1.f - g_buf[OF_WMIX]) : 1.f;
    #pragma unroll
    for (int i = 0; i < 4; i++) {
        int r = row0 + ty * 4 + i, c = col0 + tx * 4;
        float4 o;
        o.x = acc[i][0] * scale + (g.bias ? g.bias[c + 0] : 0.f);
        o.y = acc[i][1] * scale + (g.bias ? g.bias[c + 1] : 0.f);
        o.z = acc[i][2] * scale + (g.bias ? g.bias[c + 2] : 0.f);
        o.w = acc[i][3] * scale + (g.bias ? g.bias[c + 3] : 0.f);
        if (g.round) { o.x = rtf(o.x); o.y = rtf(o.y); o.z = rtf(o.z); o.w = rtf(o.w); }
        *(float4*)&g.C[(size_t)r * g.ldc + c] = o;
    }
}

// ---------------- big tf32 GEMM: 128x128 tiles, 256 threads ----------------------
// mode: 0 plain, 1 Z1 epilogue (silu+biases, A generated on the fly),
//       2 scores epilogue, 3 QG (cols<256 -> write Q; cols>=256 -> gate reduce)
struct MArgs {
    const float* A; const float* B; float* C;
    int K, lda, ldb, ldc, transB, mode, round, gen_a;
    long sA, sB, sC;
    const float *w1a, *b1a, *w1b, *b1b;
};

__device__ __forceinline__ void mma_tf32(float (&c)[4], const unsigned (&a)[4], const unsigned (&b)[2])
{
    asm volatile(
        "mma.sync.aligned.m16n8k8.row.col.f32.tf32.tf32.f32 "
        "{%0,%1,%2,%3}, {%4,%5,%6,%7}, {%8,%9}, {%0,%1,%2,%3};"
        : "+f"(c[0]), "+f"(c[1]), "+f"(c[2]), "+f"(c[3])
        : "r"(a[0]), "r"(a[1]), "r"(a[2]), "r"(a[3]), "r"(b[0]), "r"(b[1]));
}

__global__ void __launch_bounds__(256) k_mma2(MArgs ar)
{
    __shared__ unsigned As[16][132];
    __shared__ unsigned Bs[16][132];
    __shared__ float s_S[128];
    int z = blockIdx.z;
    const float* A = ar.A + (size_t)z * ar.sA;
    const float* B = ar.B + (size_t)z * ar.sB;
    float*       C = ar.C + (size_t)z * ar.sC;
    int tid = threadIdx.x;
    int warp = tid >> 5, lane = tid & 31;
    int gg = lane >> 2, tig = lane & 3;
    int wm = warp >> 2, wn = warp & 3;
    int row0 = blockIdx.y * 128, col0 = blockIdx.x * 128;

    if (ar.gen_a) {
        if (tid < 128) {
            int pair = row0 + tid;
            int p = pair / kNE, e = pair - p * kNE;
            float dx = g_buf[OF_XP + p*3 + 0] - g_buf[OF_XE + e*3 + 0];
            float dy = g_buf[OF_XP + p*3 + 1] - g_buf[OF_XE + e*3 + 1];
            float dz = g_buf[OF_XP + p*3 + 2] - g_buf[OF_XE + e*3 + 2];
            s_S[tid] = dx*dx + dy*dy + dz*dz;
        }
        __syncthreads();
    }

    float c[4][4][4] = {};
    for (int k0 = 0; k0 < ar.K; k0 += 16) {
        #pragma unroll
        for (int q = 0; q < 2; q++) {
            int t = tid + q * 256;
            int r = t >> 2, cc = (t & 3) * 4;
            if (!ar.gen_a) {
                float4 a4 = *(const float4*)&A[(size_t)(row0 + r) * ar.lda + k0 + cc];
                As[cc + 0][r] = __float_as_uint(a4.x);
                As[cc + 1][r] = __float_as_uint(a4.y);
                As[cc + 2][r] = __float_as_uint(a4.z);
                As[cc + 3][r] = __float_as_uint(a4.w);
            } else {
                float S = s_S[r];
                #pragma unroll
                for (int x = 0; x < 4; x++) {
                    int k = k0 + cc + x;
                    float w = (k < kD) ? ar.w1a[k] : ar.w1b[k - kD];
                    float b = (k < kD) ? ar.b1a[k] : ar.b1b[k - kD];
                    As[cc + x][r] = f2tf(fsilu(fmaf(S, w, b)));
                }
            }
            if (!ar.transB) {
                int kk = t >> 5, c2 = (t & 31) * 4;
                float4 b4 = *(const float4*)&B[(size_t)(k0 + kk) * ar.ldb + col0 + c2];
                uint4 u;
                u.x = __float_as_uint(b4.x); u.y = __float_as_uint(b4.y);
                u.z = __float_as_uint(b4.z); u.w = __float_as_uint(b4.w);
                *(uint4*)&Bs[kk][c2] = u;
            } else {
                float4 b4 = *(const float4*)&B[(size_t)(col0 + r) * ar.ldb + k0 + cc];
                Bs[cc + 0][r] = __float_as_uint(b4.x);
                Bs[cc + 1][r] = __float_as_uint(b4.y);
                Bs[cc + 2][r] = __float_as_uint(b4.z);
                Bs[cc + 3][r] = __float_as_uint(b4.w);
            }
        }
        __syncthreads();
        #pragma unroll
        for (int ks = 0; ks < 2; ks++) {
            unsigned af[4][4], bf[4][2];
            #pragma unroll
            for (int i = 0; i < 4; i++) {
                int m = wm * 64 + i * 16;
                af[i][0] = As[ks*8 + tig    ][m + gg    ];
                af[i][1] = As[ks*8 + tig    ][m + gg + 8];
                af[i][2] = As[ks*8 + tig + 4][m + gg    ];
                af[i][3] = As[ks*8 + tig + 4][m + gg + 8];
            }
            #pragma unroll
            for (int j = 0; j < 4; j++) {
                int n = wn * 32 + j * 8;
                bf[j][0] = Bs[ks*8 + tig    ][n + gg];
                bf[j][1] = Bs[ks*8 + tig + 4][n + gg];
            }
            #pragma unroll
            for (int i = 0; i < 4; i++)
                #pragma unroll
                for (int j = 0; j < 4; j++)
                    mma_tf32(c[i][j], af[i], bf[j]);
        }
        __syncthreads();
    }

    // ---- gate-reduce epilogue (QG kernel, gate column tiles) ----
    if (ar.mode == 3 && col0 >= kD) {
        int p = row0 / kNE;
        float part[4][2] = {};
        #pragma unroll
        for (int j = 0; j < 4; j++) {
            int gcol = col0 - kD + wn * 32 + j * 8 + tig * 2;
            float bg0 = g_buf[OF_BG + gcol], bg1 = g_buf[OF_BG + gcol + 1];
            #pragma unroll
            for (int i = 0; i < 4; i++) {
                #pragma unroll
                for (int h = 0; h < 2; h++) {
                    int r = row0 + wm * 64 + i * 16 + gg + h * 8;
                    int e = r - p * kNE;
                    const float* hw = g_buf + OF_HEWR + (size_t)e * kD + gcol;
                    part[j][0] += fsigm(c[i][j][h*2]     + bg0) * hw[0];
                    part[j][1] += fsigm(c[i][j][h*2 + 1] + bg1) * hw[1];
                }
            }
        }
        #pragma unroll
        for (int j = 0; j < 4; j++) {
            #pragma unroll
            for (int o = 16; o >= 4; o >>= 1) {
                part[j][0] += __shfl_xor_sync(0xffffffffu, part[j][0], o);
                part[j][1] += __shfl_xor_sync(0xffffffffu, part[j][1], o);
            }
        }
        if (gg == 0) {
            #pragma unroll
            for (int j = 0; j < 4; j++) {
                int gcol = col0 - kD + wn * 32 + j * 8 + tig * 2;
                atomicAdd(&g_buf[OF_T + (size_t)p * kD + gcol],     part[j][0]);
                atomicAdd(&g_buf[OF_T + (size_t)p * kD + gcol + 1], part[j][1]);
            }
        }
        return;
    }

    // ---- standard epilogues ----
    #pragma unroll
    for (int i = 0; i < 4; i++) {
        #pragma unroll
        for (int j = 0; j < 4; j++) {
            int r0 = row0 + wm * 64 + i * 16 + gg;
            int cc = col0 + wn * 32 + j * 8 + tig * 2;
            #pragma unroll
            for (int h = 0; h < 2; h++) {
                int r = r0 + h * 8;
                float v0 = c[i][j][h * 2], v1 = c[i][j][h * 2 + 1];
                if (ar.mode == 1) {
                    int p = r / kNE, e = r - p * kNE;
                    v0 = fsilu(v0 + g_buf[OF_CVEC + cc]     + g_buf[OF_HPW1A + (size_t)p*kD + cc]
                                   + g_buf[OF_HEW1B + (size_t)e*kD + cc]);
                    v1 = fsilu(v1 + g_buf[OF_CVEC + cc + 1] + g_buf[OF_HPW1A + (size_t)p*kD + cc + 1]
                                   + g_buf[OF_HEW1B + (size_t)e*kD + cc + 1]);
                } else if (ar.mode == 2) {
                    float add = g_buf[OF_U + (size_t)z*kNE + r] + g_buf[OF_C0];
                    v0 = (v0 + add + g_buf[OF_V + (size_t)z*kNE + cc]) * 0.0625f;
                    v1 = (v1 + add + g_buf[OF_V + (size_t)z*kNE + cc + 1]) * 0.0625f;
                }
                if (ar.round) { v0 = rtf(v0); v1 = rtf(v1); }
                float2 o; o.x = v0; o.y = v1;
                *(float2*)&C[(size_t)r * ar.ldc + cc] = o;
            }
        }
    }
}

// ---------------- u,v per pair ----------------------------------------------------
__global__ void __launch_bounds__(256) k_uv()
{
    int warp = threadIdx.x >> 5, lane = threadIdx.x & 31;
    size_t pair = (size_t)blockIdx.x * 8 + warp;
    const float* zz = g_buf + OF_Z1 + pair * kD;
    float su = 0.f, sv = 0.f;
    #pragma unroll
    for (int q = 0; q < 8; q++) {
        int d = lane + q * 32;
        float zv = zz[d];
        su += zv * g_buf[OF_VQ + d];
        sv += zv * g_buf[OF_VK + d];
    }
    #pragma unroll
    for (int o = 16; o; o >>= 1) {
        su += __shfl_xor_sync(0xffffffffu, su, o);
        sv += __shfl_xor_sync(0xffffffffu, sv, o);
    }
    if (lane == 0) { g_buf[OF_U + pair] = su; g_buf[OF_V + pair] = sv; }
}

// ---------------- softmax row stats ------------------------------------------------
__global__ void __launch_bounds__(256) k_rowstats()
{
    int warp = threadIdx.x >> 5, lane = threadIdx.x & 31;
    size_t row = (size_t)blockIdx.x * 8 + warp;
    const float* s = g_buf + OF_SC + row * kNE;
    float v[12];
    float mx = -1e30f;
    #pragma unroll
    for (int i = 0; i < 12; i++) { v[i] = s[lane + 32*i]; mx = fmaxf(mx, v[i]); }
    #pragma unroll
    for (int o = 16; o; o >>= 1) mx = fmaxf(mx, __shfl_xor_sync(0xffffffffu, mx, o));
    float sum = 0.f;
    #pragma unroll
    for (int i = 0; i < 12; i++) sum += fexpf_(v[i] - mx);
    #pragma unroll
    for (int o = 16; o; o >>= 1) sum += __shfl_xor_sync(0xffffffffu, sum, o);
    if (lane == 0) {
        g_buf[OF_RMAX + row] = mx;
        g_buf[OF_RINV + row] = frcpf_(sum);
    }
}

__global__ void __launch_bounds__(256) k_acol()
{
    int idx = blockIdx.x * 256 + threadIdx.x;
    int p = idx / kNE, f = idx - p * kNE;
    const float* base = g_buf + OF_SC + (size_t)p * kNE * kNE + f;
    const float* rm = g_buf + OF_RMAX + (size_t)p * kNE;
    const float* ri = g_buf + OF_RINV + (size_t)p * kNE;
    float s = 0.f;
    #pragma unroll 8
    for (int e = 0; e < kNE; e++)
        s += fexpf_(base[(size_t)e * kNE] - rm[e]) * ri[e];
    g_buf[OF_ACOL + idx] = s * (1.f / kNE);
}

__global__ void __launch_bounds__(256) k_y1()
{
    int p = blockIdx.x, d = threadIdx.x;
    __shared__ float ac[kNE];
    for (int i = d; i < kNE; i += 256) ac[i] = g_buf[OF_ACOL + (size_t)p * kNE + i];
    __syncthreads();
    float s = 0.f;
    const float* zz = g_buf + OF_Z1 + (size_t)p * kNE * kD + d;
    #pragma unroll 8
    for (int f = 0; f < kNE; f++) s += ac[f] * zz[(size_t)f * kD];
    g_buf[OF_Y1 + (size_t)p * kD + d] = s;
}

// ---------------- final ---------------------------------------------------------------
__global__ void k_final(const float* __restrict__ H, float* __restrict__ out)
{
    int n = blockIdx.x, d = threadIdx.x;
    int p = g_ibuf[kNP + kNE + n];
    float v = H[(size_t)n * kD + d];
    if (p >= 0)
        v = g_buf[OF_HPWL + (size_t)p * kD + d] * g_buf[OF_T + (size_t)p * kD + d] * (1.f / kNE)
          + g_buf[OF_Y2 + (size_t)p * kD + d];
    out[(size_t)n * kD + d] = v;
}

// ---------------- launch ---------------------------------------------------------------
extern "C" void kernel_launch(void* const* d_in, const int* in_sizes, int n_in,
                              void* d_out, int out_size)
{
    const float* H   = (const float*)d_in[0];
    const float* X   = (const float*)d_in[1];
    const unsigned char* pm = (const unsigned char*)d_in[2];
    const unsigned char* em = (const unsigned char*)d_in[3];
    const float* rw1 = (const float*)d_in[4];
    const float* rb1 = (const float*)d_in[5];
    const float* rw2 = (const float*)d_in[6];
    const float* rb2 = (const float*)d_in[7];
    const float* aw1 = (const float*)d_in[8];
    const float* ab1 = (const float*)d_in[9];
    const float* aw2 = (const float*)d_in[10];
    const float* ab2 = (const float*)d_in[11];
    const float* simw= (const float*)d_in[12];
    const float* iw1 = (const float*)d_in[13];
    const float* ib1 = (const float*)d_in[14];
    const float* iw2 = (const float*)d_in[15];
    const float* ib2 = (const float*)d_in[16];
    const float* wl  = (const float*)d_in[17];
    const float* wr  = (const float*)d_in[18];
    const float* wgw = (const float*)d_in[19];
    const float* wgb = (const float*)d_in[20];
    const float* wqw = (const float*)d_in[21];
    const float* wqb = (const float*)d_in[22];
    const float* wkw = (const float*)d_in[23];
    const float* wkb = (const float*)d_in[24];
    const float* wvw = (const float*)d_in[25];
    const float* wvb = (const float*)d_in[26];
    float* out = (float*)d_out;

    float* gb = nullptr; int* gi = nullptr;
    cudaGetSymbolAddress((void**)&gb, g_buf);
    cudaGetSymbolAddress((void**)&gi, g_ibuf);

    k_setup<<<1, 256>>>(X, pm, em, simw);
    k_vectors<<<1, 256>>>(rb2, ab2, iw1, ib1, ib2, wqw, wqb, wkw, wkb, wvw, wvb, wgw, wgb);

    GBatch batch;
    const float* W1c = iw1 + 2 * kD * kD;
    batch.d[0] = {rw2, nullptr, W1c, nullptr, gb + OF_M,             0, 0, kD,  kD,    1};
    batch.d[1] = {aw2, nullptr, W1c, nullptr, gb + OF_M + kD*kD,     0, 1, kD,  kD,    1};
    batch.d[2] = {iw2, nullptr, wqw, nullptr, gb + OF_WQ,            0, 2, kD,  kD,    0};
    batch.d[3] = {iw2, nullptr, wkw, nullptr, gb + OF_WK,            0, 2, kD,  kD,    0};
    batch.d[4] = {iw2, nullptr, wvw, nullptr, gb + OF_WV,            0, 2, kD,  kD,    0};
    batch.d[5] = {iw2, nullptr, wgw, nullptr, gb + OF_WQKG + kD,     0, 2, kD,  2*kD,  1};
    batch.d[6] = {H, gi,        iw1,          nullptr, gb + OF_HPW1A, 0, 2, kNP, kD,   0};
    batch.d[7] = {H, gi + kNP,  iw1 + kD*kD,  nullptr, gb + OF_HEW1B, 0, 2, kNE, kD,   0};
    batch.d[8] = {H, gi,        wl,           nullptr, gb + OF_HPWL,  0, 2, kNP, kD,   0};
    batch.d[9] = {H, gi + kNP,  wr,           nullptr, gb + OF_HEWR,  0, 2, kNE, kD,   0};
    k_gemm_b<<<dim3(4, 6, 10), 256>>>(batch);

    k_vqvk<<<256, 256>>>();

    GBatch b2;
    b2.d[0] = {gb + OF_WQ, nullptr, gb + OF_WK, nullptr, gb + OF_WQKG, 1, 2, kD, 2*kD, 1};
    k_gemm_b<<<dim3(4, 4, 1), 256>>>(b2);

    k_zeroT<<<kNP, 256>>>();

    // Z1 = silu(U @ M + biases); U generated on the fly from S
    MArgs mz = {};
    mz.A = nullptr; mz.B = gb + OF_M; mz.C = gb + OF_Z1;
    mz.K = 512; mz.lda = 512; mz.ldb = kD; mz.ldc = kD;
    mz.transB = 0; mz.mode = 1; mz.round = 1; mz.gen_a = 1;
    mz.w1a = rw1; mz.b1a = rb1; mz.w1b = aw1; mz.b1b = ab1;
    k_mma2<<<dim3(2, kPairs / 128, 1), 256>>>(mz);

    k_uv<<<kPairs / 8, 256>>>();

    // QG: Q = Z1 @ WQK (written), gate = Z1 @ WG' (reduced into T in-epilogue)
    MArgs mq = {};
    mq.A = gb + OF_Z1; mq.B = gb + OF_WQKG; mq.C = gb + OF_Q;
    mq.K = kD; mq.lda = kD; mq.ldb = 2*kD; mq.ldc = kD;
    mq.transB = 0; mq.mode = 3; mq.round = 1; mq.gen_a = 0;
    k_mma2<<<dim3(4, kPairs / 128, 1), 256>>>(mq);

    // scores[p] = (Q[p] @ Z1[p]^T + u + v + c0) / 16
    MArgs ms = {};
    ms.A = gb + OF_Q; ms.B = gb + OF_Z1; ms.C = gb + OF_SC;
    ms.K = kD; ms.lda = kD; ms.ldb = kD; ms.ldc = kNE;
    ms.transB = 1; ms.mode = 2; ms.round = 0; ms.gen_a = 0;
    ms.sA = (long)kNE * kD; ms.sB = (long)kNE * kD; ms.sC = (long)kNE * kNE;
    k_mma2<<<dim3(3, 3, kNP), 256>>>(ms);

    k_rowstats<<<kPairs / 8, 256>>>();
    k_acol<<<kPairs / 256, 256>>>();
    k_y1<<<kNP, 256>>>();

    GBatch b3;
    b3.d[0] = {gb + OF_Y1, nullptr, gb + OF_WV, gb + OF_BV, gb + OF_Y2, 0, 2, kNP, kD, 0};
    k_gemm_b<<<dim3(4, 6, 1), 256>>>(b3);

    k_final<<<kN, 256>>>(H, out);
}